// round 2
// baseline (speedup 1.0000x reference)
#include <cuda_runtime.h>
#include <cstdint>

// CFConv: y[idx_i[e]] += x[idx_j[e]] * Wij[e]  (elementwise over F=64), idx_i sorted.
// E ~ 1.25M, N = 50000, F = 64.
//
// Strategy:
//  - 16 threads ("lanes") per edge-chain; each lane owns a float4 slice of the
//    64-float feature row -> 256B coalesced reads of Wij and of the gathered x row.
//  - idx_i is sorted: accumulate the running segment in registers, flush with
//    atomicAdd (compiles to RED.E.ADD.F32, no return) only on segment change or
//    chunk boundary. ~25 edges/atom -> ~3-5M atomics total instead of 80M.
//  - Output zeroed with cudaMemsetAsync (graph-capturable memset node).
//  - Index dtype (int32 vs int64) detected at runtime from idx_j's odd 32-bit
//    words (values < 50000, so int64 little-endian => odd words are all zero).

#define F_DIM 64
#define VEC 4
#define LANES (F_DIM / VEC)        // 16 threads per edge-chain
#define GROUPS_PER_BLOCK 16        // 256 threads per block
#define THREADS (LANES * GROUPS_PER_BLOCK)
#define CHUNK 128                  // edges per group

__device__ int g_idx_is_64;

__global__ void detect_idx_kernel(const int* __restrict__ idx_j_words) {
    // idx_j values are uniform random in [0, 50000). If stored as int64 (LE),
    // every odd 32-bit word is 0. For int32, 16 consecutive odd words all being
    // zero has probability ~(1/50000)^16.
    int all_zero = 1;
    #pragma unroll
    for (int k = 1; k <= 31; k += 2) {
        all_zero &= (idx_j_words[k] == 0);
    }
    g_idx_is_64 = all_zero;
}

template <typename IdxT>
__device__ __forceinline__ void run_group(const float* __restrict__ x,
                                          const float* __restrict__ Wij,
                                          const IdxT* __restrict__ idx_i,
                                          const IdxT* __restrict__ idx_j,
                                          float* __restrict__ y,
                                          long long e0, long long e1, int lane) {
    const int fo = lane * VEC;
    long long cur = (long long)__ldg(idx_i + e0);
    float4 acc = make_float4(0.f, 0.f, 0.f, 0.f);

    for (long long e = e0; e < e1; ++e) {
        long long i = (long long)__ldg(idx_i + e);
        long long j = (long long)__ldg(idx_j + e);
        float4 w  = *reinterpret_cast<const float4*>(Wij + e * F_DIM + fo);
        float4 xv = *reinterpret_cast<const float4*>(x   + j * F_DIM + fo);
        if (i != cur) {
            float* p = y + cur * F_DIM + fo;
            atomicAdd(p + 0, acc.x);
            atomicAdd(p + 1, acc.y);
            atomicAdd(p + 2, acc.z);
            atomicAdd(p + 3, acc.w);
            acc = make_float4(0.f, 0.f, 0.f, 0.f);
            cur = i;
        }
        acc.x += xv.x * w.x;
        acc.y += xv.y * w.y;
        acc.z += xv.z * w.z;
        acc.w += xv.w * w.w;
    }
    float* p = y + cur * F_DIM + fo;
    atomicAdd(p + 0, acc.x);
    atomicAdd(p + 1, acc.y);
    atomicAdd(p + 2, acc.z);
    atomicAdd(p + 3, acc.w);
}

__global__ __launch_bounds__(THREADS) void cfconv_kernel(
    const float* __restrict__ x,
    const float* __restrict__ Wij,
    const void* __restrict__ idx_i,
    const void* __restrict__ idx_j,
    float* __restrict__ y,
    long long E) {
    const int group = blockIdx.x * GROUPS_PER_BLOCK + (threadIdx.x / LANES);
    const int lane = threadIdx.x % LANES;
    const long long e0 = (long long)group * CHUNK;
    if (e0 >= E) return;
    long long e1 = e0 + CHUNK;
    if (e1 > E) e1 = E;

    if (g_idx_is_64) {
        run_group<long long>(x, Wij, (const long long*)idx_i,
                             (const long long*)idx_j, y, e0, e1, lane);
    } else {
        run_group<int>(x, Wij, (const int*)idx_i,
                       (const int*)idx_j, y, e0, e1, lane);
    }
}

extern "C" void kernel_launch(void* const* d_in, const int* in_sizes, int n_in,
                              void* d_out, int out_size) {
    const float* x   = (const float*)d_in[0];
    const float* Wij = (const float*)d_in[1];
    const void*  idx_i = d_in[2];
    const void*  idx_j = d_in[3];
    float* y = (float*)d_out;

    const long long E = (long long)in_sizes[2];

    // Zero the output (harness poisons it with 0xAA).
    cudaMemsetAsync(d_out, 0, (size_t)out_size * sizeof(float));

    // Detect int32 vs int64 indices.
    detect_idx_kernel<<<1, 1>>>((const int*)idx_j);

    const long long groups = (E + CHUNK - 1) / CHUNK;
    const int blocks = (int)((groups + GROUPS_PER_BLOCK - 1) / GROUPS_PER_BLOCK);
    cfconv_kernel<<<blocks, THREADS>>>(x, Wij, idx_i, idx_j, y, E);
}

// round 3
// speedup vs baseline: 1.3802x; 1.3802x over previous
#include <cuda_runtime.h>
#include <cstdint>

// CFConv: y[idx_i[e]] += x[idx_j[e]] * Wij[e]  (F=64), idx_i sorted.
// E ~ 1.25M, N = 50000.
//
// R2: latency-bound fix. Cooperative coalesced index loads + shuffle broadcast,
// unroll-4 load batching (MLP~8), CHUNK=64 for grid-level occupancy.
// Indices read as low 32-bit word with runtime stride (int32 vs int64).

#define F_DIM 64
#define LANES 16                 // threads per edge-chain (float4 slice each)
#define GPB   16                 // groups per block -> 256 threads
#define THREADS (LANES * GPB)
#define CHUNK 64                 // edges per group

__device__ int g_idx_stride;     // 1 = int32 indices, 2 = int64 (read low word)

__global__ void detect_idx_kernel(const int* __restrict__ idx_j_words) {
    // values are uniform in [0,50000): if int64 (LE), all odd words are 0.
    int all_zero = 1;
    #pragma unroll
    for (int k = 1; k <= 31; k += 2) all_zero &= (idx_j_words[k] == 0);
    g_idx_stride = all_zero ? 2 : 1;
}

__device__ __forceinline__ void flush_acc(float* __restrict__ y, int cur, int fo,
                                          float4& acc) {
    float* p = y + (long long)cur * F_DIM + fo;
    atomicAdd(p + 0, acc.x);
    atomicAdd(p + 1, acc.y);
    atomicAdd(p + 2, acc.z);
    atomicAdd(p + 3, acc.w);
    acc = make_float4(0.f, 0.f, 0.f, 0.f);
}

__global__ __launch_bounds__(THREADS) void cfconv_kernel(
    const float* __restrict__ x,
    const float* __restrict__ Wij,
    const int* __restrict__ idx_i,
    const int* __restrict__ idx_j,
    float* __restrict__ y,
    long long E) {
    const int stride = g_idx_stride;
    const int lane = threadIdx.x & (LANES - 1);
    const unsigned mask = 0xFFFFu << (threadIdx.x & 16);   // half-warp group mask
    const long long group = (long long)blockIdx.x * GPB + (threadIdx.x >> 4);
    long long e0 = group * CHUNK;
    if (e0 >= E) return;
    long long e1 = e0 + CHUNK;
    if (e1 > E) e1 = E;

    const int fo = lane * 4;
    const float* __restrict__ wb = Wij + fo;
    const float* __restrict__ xb = x + fo;

    int cur = __ldg(idx_i + e0 * stride);
    float4 acc = make_float4(0.f, 0.f, 0.f, 0.f);

    long long base = e0;

    // Prefetch first index batch (coalesced: lane l loads edge base+l).
    int my_i = 0, my_j = 0;
    if (base + LANES <= e1) {
        my_i = __ldg(idx_i + (base + lane) * stride);
        my_j = __ldg(idx_j + (base + lane) * stride);
    }

    for (; base + LANES <= e1; base += LANES) {
        // Prefetch next batch's indices while processing this one.
        int nx_i = 0, nx_j = 0;
        if (base + 2 * LANES <= e1) {
            nx_i = __ldg(idx_i + (base + LANES + lane) * stride);
            nx_j = __ldg(idx_j + (base + LANES + lane) * stride);
        }

        #pragma unroll
        for (int k0 = 0; k0 < LANES; k0 += 4) {
            // Broadcast 4 edges' gather indices.
            int j0 = __shfl_sync(mask, my_j, k0 + 0, LANES);
            int j1 = __shfl_sync(mask, my_j, k0 + 1, LANES);
            int j2 = __shfl_sync(mask, my_j, k0 + 2, LANES);
            int j3 = __shfl_sync(mask, my_j, k0 + 3, LANES);

            // Issue all 8 loads before consuming anything (MLP ~ 8).
            float4 w0 = __ldg((const float4*)(wb + (base + k0 + 0) * F_DIM));
            float4 w1 = __ldg((const float4*)(wb + (base + k0 + 1) * F_DIM));
            float4 w2 = __ldg((const float4*)(wb + (base + k0 + 2) * F_DIM));
            float4 w3 = __ldg((const float4*)(wb + (base + k0 + 3) * F_DIM));
            float4 x0 = __ldg((const float4*)(xb + (long long)j0 * F_DIM));
            float4 x1 = __ldg((const float4*)(xb + (long long)j1 * F_DIM));
            float4 x2 = __ldg((const float4*)(xb + (long long)j2 * F_DIM));
            float4 x3 = __ldg((const float4*)(xb + (long long)j3 * F_DIM));

            int i0 = __shfl_sync(mask, my_i, k0 + 0, LANES);
            int i1 = __shfl_sync(mask, my_i, k0 + 1, LANES);
            int i2 = __shfl_sync(mask, my_i, k0 + 2, LANES);
            int i3 = __shfl_sync(mask, my_i, k0 + 3, LANES);

            if (i0 != cur) { flush_acc(y, cur, fo, acc); cur = i0; }
            acc.x += x0.x * w0.x; acc.y += x0.y * w0.y;
            acc.z += x0.z * w0.z; acc.w += x0.w * w0.w;

            if (i1 != cur) { flush_acc(y, cur, fo, acc); cur = i1; }
            acc.x += x1.x * w1.x; acc.y += x1.y * w1.y;
            acc.z += x1.z * w1.z; acc.w += x1.w * w1.w;

            if (i2 != cur) { flush_acc(y, cur, fo, acc); cur = i2; }
            acc.x += x2.x * w2.x; acc.y += x2.y * w2.y;
            acc.z += x2.z * w2.z; acc.w += x2.w * w2.w;

            if (i3 != cur) { flush_acc(y, cur, fo, acc); cur = i3; }
            acc.x += x3.x * w3.x; acc.y += x3.y * w3.y;
            acc.z += x3.z * w3.z; acc.w += x3.w * w3.w;
        }

        my_i = nx_i;
        my_j = nx_j;
    }

    // Scalar tail (< LANES edges).
    for (; base < e1; ++base) {
        int i = __ldg(idx_i + base * stride);
        int j = __ldg(idx_j + base * stride);
        float4 w  = __ldg((const float4*)(wb + base * F_DIM));
        float4 xv = __ldg((const float4*)(xb + (long long)j * F_DIM));
        if (i != cur) { flush_acc(y, cur, fo, acc); cur = i; }
        acc.x += xv.x * w.x; acc.y += xv.y * w.y;
        acc.z += xv.z * w.z; acc.w += xv.w * w.w;
    }

    flush_acc(y, cur, fo, acc);
}

extern "C" void kernel_launch(void* const* d_in, const int* in_sizes, int n_in,
                              void* d_out, int out_size) {
    const float* x   = (const float*)d_in[0];
    const float* Wij = (const float*)d_in[1];
    const int*   idx_i = (const int*)d_in[2];
    const int*   idx_j = (const int*)d_in[3];
    float* y = (float*)d_out;

    const long long E = (long long)in_sizes[2];

    cudaMemsetAsync(d_out, 0, (size_t)out_size * sizeof(float));
    detect_idx_kernel<<<1, 1>>>((const int*)d_in[3]);

    const long long groups = (E + CHUNK - 1) / CHUNK;
    const int blocks = (int)((groups + GPB - 1) / GPB);
    cfconv_kernel<<<blocks, THREADS>>>(x, Wij, idx_i, idx_j, y, E);
}

// round 4
// speedup vs baseline: 1.4651x; 1.0615x over previous
#include <cuda_runtime.h>
#include <cstdint>

// CFConv: y[idx_i[e]] += x[idx_j[e]] * Wij[e]  (F=64), idx_i sorted.
// E ~ 1.25M, N = 50000.
//
// R3: occupancy fix. regs were 68 -> 3 CTAs/SM (33.8% occ). Force 64 regs via
// __launch_bounds__(256,4) -> 4 CTAs/SM (50%). Streaming loads (__ldcs) for
// Wij + idx so the 320MB Wij stream doesn't evict the 12.8MB x set from L2.

#define F_DIM 64
#define LANES 16                 // threads per edge-chain (float4 slice each)
#define GPB   16                 // groups per block -> 256 threads
#define THREADS (LANES * GPB)
#define CHUNK 64                 // edges per group

__device__ int g_idx_stride;     // 1 = int32 indices, 2 = int64 (read low word)

__global__ void detect_idx_kernel(const int* __restrict__ idx_j_words) {
    // values are uniform in [0,50000): if int64 (LE), all odd words are 0.
    int all_zero = 1;
    #pragma unroll
    for (int k = 1; k <= 31; k += 2) all_zero &= (idx_j_words[k] == 0);
    g_idx_stride = all_zero ? 2 : 1;
}

__device__ __forceinline__ void flush_acc(float* __restrict__ y, int cur, int fo,
                                          float4& acc) {
    float* p = y + (long long)cur * F_DIM + fo;
    atomicAdd(p + 0, acc.x);
    atomicAdd(p + 1, acc.y);
    atomicAdd(p + 2, acc.z);
    atomicAdd(p + 3, acc.w);
    acc = make_float4(0.f, 0.f, 0.f, 0.f);
}

__global__ __launch_bounds__(THREADS, 4) void cfconv_kernel(
    const float* __restrict__ x,
    const float* __restrict__ Wij,
    const int* __restrict__ idx_i,
    const int* __restrict__ idx_j,
    float* __restrict__ y,
    long long E) {
    const int stride = g_idx_stride;
    const int lane = threadIdx.x & (LANES - 1);
    const unsigned mask = 0xFFFFu << (threadIdx.x & 16);   // half-warp group mask
    const long long group = (long long)blockIdx.x * GPB + (threadIdx.x >> 4);
    long long e0 = group * CHUNK;
    if (e0 >= E) return;
    long long e1 = e0 + CHUNK;
    if (e1 > E) e1 = E;

    const int fo = lane * 4;
    const float* __restrict__ wb = Wij + fo;
    const float* __restrict__ xb = x + fo;

    int cur = __ldcs(idx_i + e0 * stride);
    float4 acc = make_float4(0.f, 0.f, 0.f, 0.f);

    long long base = e0;

    // Prefetch first index batch (coalesced: lane l loads edge base+l).
    int my_i = 0, my_j = 0;
    if (base + LANES <= e1) {
        my_i = __ldcs(idx_i + (base + lane) * stride);
        my_j = __ldcs(idx_j + (base + lane) * stride);
    }

    for (; base + LANES <= e1; base += LANES) {
        // Prefetch next batch's indices while processing this one.
        int nx_i = 0, nx_j = 0;
        if (base + 2 * LANES <= e1) {
            nx_i = __ldcs(idx_i + (base + LANES + lane) * stride);
            nx_j = __ldcs(idx_j + (base + LANES + lane) * stride);
        }

        #pragma unroll
        for (int k0 = 0; k0 < LANES; k0 += 4) {
            // Broadcast 4 edges' gather indices.
            int j0 = __shfl_sync(mask, my_j, k0 + 0, LANES);
            int j1 = __shfl_sync(mask, my_j, k0 + 1, LANES);
            int j2 = __shfl_sync(mask, my_j, k0 + 2, LANES);
            int j3 = __shfl_sync(mask, my_j, k0 + 3, LANES);

            // Issue all 8 loads before consuming anything (MLP ~ 8).
            // Wij is a pure stream: evict-first so it doesn't wash x out of L2.
            float4 w0 = __ldcs((const float4*)(wb + (base + k0 + 0) * F_DIM));
            float4 w1 = __ldcs((const float4*)(wb + (base + k0 + 1) * F_DIM));
            float4 w2 = __ldcs((const float4*)(wb + (base + k0 + 2) * F_DIM));
            float4 w3 = __ldcs((const float4*)(wb + (base + k0 + 3) * F_DIM));
            float4 x0 = __ldg((const float4*)(xb + (long long)j0 * F_DIM));
            float4 x1 = __ldg((const float4*)(xb + (long long)j1 * F_DIM));
            float4 x2 = __ldg((const float4*)(xb + (long long)j2 * F_DIM));
            float4 x3 = __ldg((const float4*)(xb + (long long)j3 * F_DIM));

            int i0 = __shfl_sync(mask, my_i, k0 + 0, LANES);
            int i1 = __shfl_sync(mask, my_i, k0 + 1, LANES);
            int i2 = __shfl_sync(mask, my_i, k0 + 2, LANES);
            int i3 = __shfl_sync(mask, my_i, k0 + 3, LANES);

            if (i0 != cur) { flush_acc(y, cur, fo, acc); cur = i0; }
            acc.x += x0.x * w0.x; acc.y += x0.y * w0.y;
            acc.z += x0.z * w0.z; acc.w += x0.w * w0.w;

            if (i1 != cur) { flush_acc(y, cur, fo, acc); cur = i1; }
            acc.x += x1.x * w1.x; acc.y += x1.y * w1.y;
            acc.z += x1.z * w1.z; acc.w += x1.w * w1.w;

            if (i2 != cur) { flush_acc(y, cur, fo, acc); cur = i2; }
            acc.x += x2.x * w2.x; acc.y += x2.y * w2.y;
            acc.z += x2.z * w2.z; acc.w += x2.w * w2.w;

            if (i3 != cur) { flush_acc(y, cur, fo, acc); cur = i3; }
            acc.x += x3.x * w3.x; acc.y += x3.y * w3.y;
            acc.z += x3.z * w3.z; acc.w += x3.w * w3.w;
        }

        my_i = nx_i;
        my_j = nx_j;
    }

    // Scalar tail (< LANES edges).
    for (; base < e1; ++base) {
        int i = __ldcs(idx_i + base * stride);
        int j = __ldcs(idx_j + base * stride);
        float4 w  = __ldcs((const float4*)(wb + base * F_DIM));
        float4 xv = __ldg((const float4*)(xb + (long long)j * F_DIM));
        if (i != cur) { flush_acc(y, cur, fo, acc); cur = i; }
        acc.x += xv.x * w.x; acc.y += xv.y * w.y;
        acc.z += xv.z * w.z; acc.w += xv.w * w.w;
    }

    flush_acc(y, cur, fo, acc);
}

extern "C" void kernel_launch(void* const* d_in, const int* in_sizes, int n_in,
                              void* d_out, int out_size) {
    const float* x   = (const float*)d_in[0];
    const float* Wij = (const float*)d_in[1];
    const int*   idx_i = (const int*)d_in[2];
    const int*   idx_j = (const int*)d_in[3];
    float* y = (float*)d_out;

    const long long E = (long long)in_sizes[2];

    cudaMemsetAsync(d_out, 0, (size_t)out_size * sizeof(float));
    detect_idx_kernel<<<1, 1>>>((const int*)d_in[3]);

    const long long groups = (E + CHUNK - 1) / CHUNK;
    const int blocks = (int)((groups + GPB - 1) / GPB);
    cfconv_kernel<<<blocks, THREADS>>>(x, Wij, idx_i, idx_j, y, E);
}

// round 5
// speedup vs baseline: 1.5758x; 1.0756x over previous
#include <cuda_runtime.h>
#include <cstdint>

// CFConv: y[idx_i[e]] += x[idx_j[e]] * Wij[e]  (F=64), idx_i sorted.
// E ~ 1.25M, N = 50000.
//
// R4: full-warp edge groups (32 lanes x float2 slice) to cut register pressure
// -> 5 CTAs/SM (62.5% occ cap). Inlined idx-dtype detection (no detect kernel).
// Wij streamed with __ldcs; x gathers via __ldg (L2-resident, 12.8MB set).

#define F_DIM 64
#define WPB   8                   // warps per block -> 256 threads
#define THREADS (32 * WPB)
#define CHUNK 64                  // edges per warp

__device__ __forceinline__ void flush_acc(float* __restrict__ y, int cur, int fo,
                                          float2& acc) {
    float* p = y + (long long)cur * F_DIM + fo;
    atomicAdd(p + 0, acc.x);
    atomicAdd(p + 1, acc.y);
    acc.x = 0.f; acc.y = 0.f;
}

__global__ __launch_bounds__(THREADS, 5) void cfconv_kernel(
    const float* __restrict__ x,
    const float* __restrict__ Wij,
    const int* __restrict__ idx_i,
    const int* __restrict__ idx_j,
    float* __restrict__ y,
    long long E) {
    // Inline idx dtype detection: values < 50000, so int64 (LE) => odd 32-bit
    // words all zero. 16 broadcast loads, L1-hit after the first, uniform result.
    int all_zero = 1;
    #pragma unroll
    for (int k = 1; k <= 31; k += 2) all_zero &= (__ldg(idx_j + k) == 0);
    const int stride = all_zero ? 2 : 1;

    const int lane = threadIdx.x & 31;
    const long long warp = (long long)blockIdx.x * WPB + (threadIdx.x >> 5);
    long long e0 = warp * CHUNK;
    if (e0 >= E) return;
    long long e1 = e0 + CHUNK;
    if (e1 > E) e1 = E;

    const int fo = lane * 2;
    const float* __restrict__ wb = Wij + fo;
    const float* __restrict__ xb = x + fo;

    int cur = __ldg(idx_i + e0 * stride);
    float2 acc = make_float2(0.f, 0.f);

    long long base = e0;

    // Prefetch first index batch (coalesced: lane l loads edge base+l).
    int my_i = 0, my_j = 0;
    if (base + 32 <= e1) {
        my_i = __ldg(idx_i + (base + lane) * stride);
        my_j = __ldg(idx_j + (base + lane) * stride);
    }

    for (; base + 32 <= e1; base += 32) {
        int nx_i = 0, nx_j = 0;
        if (base + 64 <= e1) {
            nx_i = __ldg(idx_i + (base + 32 + lane) * stride);
            nx_j = __ldg(idx_j + (base + 32 + lane) * stride);
        }

        #pragma unroll
        for (int k0 = 0; k0 < 32; k0 += 4) {
            int j0 = __shfl_sync(0xFFFFFFFFu, my_j, k0 + 0);
            int j1 = __shfl_sync(0xFFFFFFFFu, my_j, k0 + 1);
            int j2 = __shfl_sync(0xFFFFFFFFu, my_j, k0 + 2);
            int j3 = __shfl_sync(0xFFFFFFFFu, my_j, k0 + 3);

            // Issue all 8 loads before consuming anything.
            float2 w0 = __ldcs((const float2*)(wb + (base + k0 + 0) * F_DIM));
            float2 w1 = __ldcs((const float2*)(wb + (base + k0 + 1) * F_DIM));
            float2 w2 = __ldcs((const float2*)(wb + (base + k0 + 2) * F_DIM));
            float2 w3 = __ldcs((const float2*)(wb + (base + k0 + 3) * F_DIM));
            float2 x0 = __ldg((const float2*)(xb + (long long)j0 * F_DIM));
            float2 x1 = __ldg((const float2*)(xb + (long long)j1 * F_DIM));
            float2 x2 = __ldg((const float2*)(xb + (long long)j2 * F_DIM));
            float2 x3 = __ldg((const float2*)(xb + (long long)j3 * F_DIM));

            int i0 = __shfl_sync(0xFFFFFFFFu, my_i, k0 + 0);
            int i1 = __shfl_sync(0xFFFFFFFFu, my_i, k0 + 1);
            int i2 = __shfl_sync(0xFFFFFFFFu, my_i, k0 + 2);
            int i3 = __shfl_sync(0xFFFFFFFFu, my_i, k0 + 3);

            if (i0 != cur) { flush_acc(y, cur, fo, acc); cur = i0; }
            acc.x += x0.x * w0.x; acc.y += x0.y * w0.y;

            if (i1 != cur) { flush_acc(y, cur, fo, acc); cur = i1; }
            acc.x += x1.x * w1.x; acc.y += x1.y * w1.y;

            if (i2 != cur) { flush_acc(y, cur, fo, acc); cur = i2; }
            acc.x += x2.x * w2.x; acc.y += x2.y * w2.y;

            if (i3 != cur) { flush_acc(y, cur, fo, acc); cur = i3; }
            acc.x += x3.x * w3.x; acc.y += x3.y * w3.y;
        }

        my_i = nx_i;
        my_j = nx_j;
    }

    // Scalar tail (< 32 edges).
    for (; base < e1; ++base) {
        int i = __ldg(idx_i + base * stride);
        int j = __ldg(idx_j + base * stride);
        float2 w  = __ldcs((const float2*)(wb + base * F_DIM));
        float2 xv = __ldg((const float2*)(xb + (long long)j * F_DIM));
        if (i != cur) { flush_acc(y, cur, fo, acc); cur = i; }
        acc.x += xv.x * w.x; acc.y += xv.y * w.y;
    }

    flush_acc(y, cur, fo, acc);
}

extern "C" void kernel_launch(void* const* d_in, const int* in_sizes, int n_in,
                              void* d_out, int out_size) {
    const float* x   = (const float*)d_in[0];
    const float* Wij = (const float*)d_in[1];
    const int*   idx_i = (const int*)d_in[2];
    const int*   idx_j = (const int*)d_in[3];
    float* y = (float*)d_out;

    const long long E = (long long)in_sizes[2];

    cudaMemsetAsync(d_out, 0, (size_t)out_size * sizeof(float));

    const long long warps = (E + CHUNK - 1) / CHUNK;
    const int blocks = (int)((warps + WPB - 1) / WPB);
    cfconv_kernel<<<blocks, THREADS>>>(x, Wij, idx_i, idx_j, y, E);
}